// round 10
// baseline (speedup 1.0000x reference)
#include <cuda_runtime.h>
#include <cstdint>

#define EPS 1e-8f

// Scratch (no allocation allowed).
__device__ float g_h1[256 * 1024];
__device__ float g_h2[256 * 1024];
__device__ float g_pC[4 * 256 * 1024];   // 4 planes L1/L2; 32*256*128 for L3
__device__ float g_Sx[256];
__device__ float g_Sh1[256];
__device__ float g_Sh2[256];
__device__ float g_Sw1[1024];
__device__ float g_Sw2[1024];
__device__ float g_Sw3[128];

// Single-instruction float min (FMNMX); inputs are finite here.
__device__ __forceinline__ float fmin1(float a, float b) {
    float r;
    asm("min.f32 %0, %1, %2;" : "=f"(r) : "f"(a), "f"(b));
    return r;
}

// ---------------------------------------------------------------------------
// Row-sum body (tree-reduced), 128 threads per row-block.
__device__ __forceinline__ void rowsum_body(const float* __restrict__ A,
                                            float* __restrict__ S,
                                            int row, int D)
{
    const float4* a = reinterpret_cast<const float4*>(A + (size_t)row * D);
    const int nq = D >> 2;
    float s = 0.0f;
    for (int q = threadIdx.x; q < nq; q += blockDim.x) {
        float4 v = a[q];
        s += (v.x + v.y) + (v.z + v.w);
    }
#pragma unroll
    for (int o = 16; o > 0; o >>= 1) s += __shfl_xor_sync(0xFFFFFFFFu, s, o);
    __shared__ float ws[32];
    const int lane = threadIdx.x & 31, w = threadIdx.x >> 5;
    if (lane == 0) ws[w] = s;
    __syncthreads();
    if (w == 0) {
        s = (lane < (int)(blockDim.x >> 5)) ? ws[lane] : 0.0f;
#pragma unroll
        for (int o = 16; o > 0; o >>= 1) s += __shfl_xor_sync(0xFFFFFFFFu, s, o);
        if (lane == 0) S[row] = s;
    }
}

// Fused row-sums for the four static inputs (all D=1024).
__global__ void rowsum4_kernel(const float* __restrict__ x,  float* __restrict__ Sx,
                               const float* __restrict__ W1, float* __restrict__ Sw1,
                               const float* __restrict__ W2, float* __restrict__ Sw2,
                               const float* __restrict__ W3, float* __restrict__ Sw3,
                               int D)
{
    int b = blockIdx.x;
    if (b < 256)            rowsum_body(x,  Sx,  b,        D);
    else if (b < 256+1024)  rowsum_body(W1, Sw1, b - 256,  D);
    else if (b < 256+2048)  rowsum_body(W2, Sw2, b - 1280, D);
    else                    rowsum_body(W3, Sw3, b - 2304, D);
}

// ---------------------------------------------------------------------------
// Min-sum partial kernel: pC[z,m,n] = sum_{k in z-slice} min(X[m,k], W[n,k]).
// BM=64, BN=128, DK=16, 512 threads (4 warps/SMSP), micro-tile 4x4.
// PTX min.f32 (1 FMNMX) + packed add.rn.f32x2 accumulators (0.5 FADD/elem).
// Double-buffered smem with ONE barrier per k-tile.
__global__ __launch_bounds__(512)
void tversky_part_kernel(const float* __restrict__ X,
                         const float* __restrict__ W,
                         float* __restrict__ pC,
                         int B, int O, int D, int kspan)
{
    constexpr int BM = 64, BN = 128, DK = 16, TM = 4, TN = 4;
    constexpr int NTX = BN / TN;          // 32 (warp = 32 tx of one ty)
    constexpr int XSTR = DK + 4;          // 20 floats (16B-aligned rows)
    constexpr int WSTR = BN + 4;          // 132 floats (16B-aligned rows)

    const int tid = threadIdx.x;
    const int tx  = tid % NTX;            // 0..31
    const int ty  = tid / NTX;            // 0..15
    const int m0  = blockIdx.y * BM;
    const int n0  = blockIdx.x * BN;
    const int k0  = blockIdx.z * kspan;

    __shared__ __align__(16) float Xs[2][BM][XSTR];   // 10,240 B
    __shared__ __align__(16) float Ws[2][DK][WSTR];   // 16,896 B

    const int xr = tid >> 2, xq = tid & 3;   // X loader: threads 0..255
    const int wr = tid >> 2, wq = tid & 3;   // W loader: all 512 threads

    const float4* Xg = reinterpret_cast<const float4*>(X + (size_t)(m0 + xr) * D + k0) + xq;
    const float4* Wg = reinterpret_cast<const float4*>(W + (size_t)(n0 + wr) * D + k0) + wq;

    // Packed accumulators: acc2[i][p] = (sum for col 2p, sum for col 2p+1).
    uint64_t acc2[TM][TN / 2];
#pragma unroll
    for (int i = 0; i < TM; i++)
#pragma unroll
        for (int p = 0; p < TN / 2; p++) acc2[i][p] = 0ull;

    const int ntiles = kspan / DK;

    // Prologue: load + store tile 0, one barrier.
    float4 xv = make_float4(0.f, 0.f, 0.f, 0.f);
    float4 wv;
    if (tid < 256) xv = Xg[0];
    wv = Wg[0];
    if (tid < 256)
        *reinterpret_cast<float4*>(&Xs[0][xr][xq * 4]) = xv;
#pragma unroll
    for (int c = 0; c < 4; c++)
        Ws[0][wq * 4 + c][wr] = (&wv.x)[c];
    __syncthreads();

    for (int t = 0; t < ntiles; t++) {
        const int buf = t & 1;
        const bool more = (t + 1 < ntiles);

        // Prefetch next tile into registers (overlaps compute).
        if (more) {
            const int off = (t + 1) * (DK / 4);
            if (tid < 256) xv = Xg[off];
            wv = Wg[off];
        }

        // Compute on current buffer.
#pragma unroll
        for (int kk = 0; kk < DK; kk += 4) {
            float4 xk[TM];
#pragma unroll
            for (int i = 0; i < TM; i++)
                xk[i] = *reinterpret_cast<const float4*>(&Xs[buf][ty * TM + i][kk]);
            float4 wk[4];
#pragma unroll
            for (int c = 0; c < 4; c++)
                wk[c] = *reinterpret_cast<const float4*>(&Ws[buf][kk + c][tx * TN]);
#pragma unroll
            for (int c = 0; c < 4; c++) {
#pragma unroll
                for (int i = 0; i < TM; i++) {
                    const float xi = (&xk[i].x)[c];
                    float m0f = fmin1(xi, wk[c].x);
                    float m1f = fmin1(xi, wk[c].y);
                    float m2f = fmin1(xi, wk[c].z);
                    float m3f = fmin1(xi, wk[c].w);
                    uint64_t p0, p1;
                    asm("mov.b64 %0, {%1, %2};" : "=l"(p0) : "f"(m0f), "f"(m1f));
                    asm("mov.b64 %0, {%1, %2};" : "=l"(p1) : "f"(m2f), "f"(m3f));
                    asm("add.rn.f32x2 %0, %0, %1;" : "+l"(acc2[i][0]) : "l"(p0));
                    asm("add.rn.f32x2 %0, %0, %1;" : "+l"(acc2[i][1]) : "l"(p1));
                }
            }
        }

        // Store prefetched tile into the other buffer, then one barrier.
        if (more) {
            const int nbuf = buf ^ 1;
            if (tid < 256)
                *reinterpret_cast<float4*>(&Xs[nbuf][xr][xq * 4]) = xv;
#pragma unroll
            for (int c = 0; c < 4; c++)
                Ws[nbuf][wq * 4 + c][wr] = (&wv.x)[c];
            __syncthreads();
        }
    }

    const size_t zb = (size_t)blockIdx.z * B * O;
#pragma unroll
    for (int i = 0; i < TM; i++) {
        float4 o4;
        asm("mov.b64 {%0, %1}, %2;" : "=f"(o4.x), "=f"(o4.y) : "l"(acc2[i][0]));
        asm("mov.b64 {%0, %1}, %2;" : "=f"(o4.z), "=f"(o4.w) : "l"(acc2[i][1]));
        *reinterpret_cast<float4*>(pC + zb + (size_t)(m0 + ty * TM + i) * O
                                   + (n0 + tx * TN)) = o4;
    }
}

// ---------------------------------------------------------------------------
// Combine NZ=4 partials + epilogue(+relu) + row-sum of result (for next layer).
// One block per output row; 256 threads, 4 cols each (O=1024).
__global__ void combine_epi_rowsum_kernel(const float* __restrict__ pC,
                                          const float* __restrict__ Sx,
                                          const float* __restrict__ Sw,
                                          float* __restrict__ h,
                                          float* __restrict__ Sh,
                                          int B, int O)
{
    const int row = blockIdx.x;
    const int j0  = threadIdx.x * 4;
    const size_t plane = (size_t)B * O;
    const size_t base  = (size_t)row * O + j0;

    float4 c0 = *reinterpret_cast<const float4*>(pC + base);
    float4 c1 = *reinterpret_cast<const float4*>(pC + plane + base);
    float4 c2 = *reinterpret_cast<const float4*>(pC + 2 * plane + base);
    float4 c3 = *reinterpret_cast<const float4*>(pC + 3 * plane + base);
    float4 sw = *reinterpret_cast<const float4*>(Sw + j0);
    const float sx = Sx[row];

    float4 o;
    o.x = fmaxf(((c0.x + c1.x) + (c2.x + c3.x)) / (0.5f * (sx + sw.x) + EPS), 0.0f);
    o.y = fmaxf(((c0.y + c1.y) + (c2.y + c3.y)) / (0.5f * (sx + sw.y) + EPS), 0.0f);
    o.z = fmaxf(((c0.z + c1.z) + (c2.z + c3.z)) / (0.5f * (sx + sw.z) + EPS), 0.0f);
    o.w = fmaxf(((c0.w + c1.w) + (c2.w + c3.w)) / (0.5f * (sx + sw.w) + EPS), 0.0f);
    *reinterpret_cast<float4*>(h + base) = o;

    // Row-sum of h for the next layer's denominator.
    float s = (o.x + o.y) + (o.z + o.w);
#pragma unroll
    for (int off = 16; off > 0; off >>= 1) s += __shfl_xor_sync(0xFFFFFFFFu, s, off);
    __shared__ float ws[8];
    const int lane = threadIdx.x & 31, w = threadIdx.x >> 5;
    if (lane == 0) ws[w] = s;
    __syncthreads();
    if (w == 0) {
        s = (lane < 8) ? ws[lane] : 0.0f;
#pragma unroll
        for (int off = 4; off > 0; off >>= 1) s += __shfl_xor_sync(0xFFFFFFFFu, s, off);
        if (lane == 0) Sh[row] = s;
    }
}

// Combine NZ partials + epilogue (final layer, no relu, no rowsum).
__global__ void combine_final_kernel(const float* __restrict__ pC,
                                     const float* __restrict__ Sx,
                                     const float* __restrict__ Sw,
                                     float* __restrict__ out,
                                     int O, int BO, int nz)
{
    int i = blockIdx.x * blockDim.x + threadIdx.x;
    if (i >= BO) return;
    float c = 0.0f;
    for (int z = 0; z < nz; z++) c += pC[(size_t)z * BO + i];
    const int m = i / O, n = i % O;
    out[i] = c / (0.5f * (Sx[m] + Sw[n]) + EPS);
}

// ---------------------------------------------------------------------------
extern "C" void kernel_launch(void* const* d_in, const int* in_sizes, int n_in,
                              void* d_out, int out_size)
{
    const float* x  = (const float*)d_in[0];   // [256, 1024]
    const float* W1 = (const float*)d_in[1];   // [1024, 1024]
    const float* W2 = (const float*)d_in[2];   // [1024, 1024]
    const float* W3 = (const float*)d_in[3];   // [128, 1024]
    float* out = (float*)d_out;                // [256, 128]

    const int B = 256, H = 1024, C = 128, D = 1024;

    float *h1, *h2, *pC, *Sx, *Sh1, *Sh2, *Sw1, *Sw2, *Sw3;
    cudaGetSymbolAddress((void**)&h1,  g_h1);
    cudaGetSymbolAddress((void**)&h2,  g_h2);
    cudaGetSymbolAddress((void**)&pC,  g_pC);
    cudaGetSymbolAddress((void**)&Sx,  g_Sx);
    cudaGetSymbolAddress((void**)&Sh1, g_Sh1);
    cudaGetSymbolAddress((void**)&Sh2, g_Sh2);
    cudaGetSymbolAddress((void**)&Sw1, g_Sw1);
    cudaGetSymbolAddress((void**)&Sw2, g_Sw2);
    cudaGetSymbolAddress((void**)&Sw3, g_Sw3);

    // Static row sums in one launch.
    rowsum4_kernel<<<256 + 1024 + 1024 + 128, 128>>>(x, Sx, W1, Sw1, W2, Sw2, W3, Sw3, D);

    // Layer 1: x vs W1, split-K=4 (grid 8x4x4 = 128 CTAs), fused combine.
    {
        dim3 grid(H / 128, B / 64, 4);
        tversky_part_kernel<<<grid, 512>>>(x, W1, pC, B, H, D, D / 4);
        combine_epi_rowsum_kernel<<<B, 256>>>(pC, Sx, Sw1, h1, Sh1, B, H);
    }
    // Layer 2: h1 vs W2, split-K=4, fused combine.
    {
        dim3 grid(H / 128, B / 64, 4);
        tversky_part_kernel<<<grid, 512>>>(h1, W2, pC, B, H, H, H / 4);
        combine_epi_rowsum_kernel<<<B, 256>>>(pC, Sh1, Sw2, h2, Sh2, B, H);
    }
    // Layer 3: h2 vs W3, split-K=32 (grid 1x4x32 = 128 CTAs), plain combine.
    {
        const int NZ = 32;
        dim3 grid(C / 128, B / 64, NZ);
        tversky_part_kernel<<<grid, 512>>>(h2, W3, pC, B, C, H, H / NZ);
        combine_final_kernel<<<(B * C + 255) / 256, 256>>>(pC, Sh2, Sw3, out, C, B * C, NZ);
    }
}

// round 11
// speedup vs baseline: 1.0833x; 1.0833x over previous
#include <cuda_runtime.h>

#define EPS 1e-8f

// Scratch (no allocation allowed).
__device__ float g_h1[256 * 1024];
__device__ float g_h2[256 * 1024];
__device__ float g_pC[8 * 256 * 1024];   // 8 planes L1/L2; 64*256*128 for L3
__device__ float g_Sx[256];
__device__ float g_Sh1[256];
__device__ float g_Sh2[256];
__device__ float g_Sw1[1024];
__device__ float g_Sw2[1024];
__device__ float g_Sw3[128];

// ---------------------------------------------------------------------------
// Row-sum body (tree-reduced), 128 threads per row-block.
__device__ __forceinline__ void rowsum_body(const float* __restrict__ A,
                                            float* __restrict__ S,
                                            int row, int D)
{
    const float4* a = reinterpret_cast<const float4*>(A + (size_t)row * D);
    const int nq = D >> 2;
    float s = 0.0f;
    for (int q = threadIdx.x; q < nq; q += blockDim.x) {
        float4 v = a[q];
        s += (v.x + v.y) + (v.z + v.w);
    }
#pragma unroll
    for (int o = 16; o > 0; o >>= 1) s += __shfl_xor_sync(0xFFFFFFFFu, s, o);
    __shared__ float ws[32];
    const int lane = threadIdx.x & 31, w = threadIdx.x >> 5;
    if (lane == 0) ws[w] = s;
    __syncthreads();
    if (w == 0) {
        s = (lane < (int)(blockDim.x >> 5)) ? ws[lane] : 0.0f;
#pragma unroll
        for (int o = 16; o > 0; o >>= 1) s += __shfl_xor_sync(0xFFFFFFFFu, s, o);
        if (lane == 0) S[row] = s;
    }
}

// Fused row-sums for the four static inputs (all D=1024).
__global__ void rowsum4_kernel(const float* __restrict__ x,  float* __restrict__ Sx,
                               const float* __restrict__ W1, float* __restrict__ Sw1,
                               const float* __restrict__ W2, float* __restrict__ Sw2,
                               const float* __restrict__ W3, float* __restrict__ Sw3,
                               int D)
{
    int b = blockIdx.x;
    if (b < 256)            rowsum_body(x,  Sx,  b,        D);
    else if (b < 256+1024)  rowsum_body(W1, Sw1, b - 256,  D);
    else if (b < 256+2048)  rowsum_body(W2, Sw2, b - 1280, D);
    else                    rowsum_body(W3, Sw3, b - 2304, D);
}

// ---------------------------------------------------------------------------
// Min-sum partial kernel: pC[z,m,n] = sum_{k in z-slice} min(X[m,k], W[n,k]).
// BM=128, BN=128, DK=16, 512 threads (4 warps/SMSP), micro-tile TM=8 x TN=4.
// Plain fminf/+= (proven codegen), double-buffered smem, ONE barrier per tile.
__global__ __launch_bounds__(512)
void tversky_part_kernel(const float* __restrict__ X,
                         const float* __restrict__ W,
                         float* __restrict__ pC,
                         int B, int O, int D, int kspan)
{
    constexpr int BM = 128, BN = 128, DK = 16, TM = 8, TN = 4;
    constexpr int NTX = BN / TN;          // 32 (warp = 32 tx of one ty)
    constexpr int XSTR = DK + 4;          // 20 floats (16B-aligned rows)
    constexpr int WSTR = BN + 4;          // 132 floats (16B-aligned rows)

    const int tid = threadIdx.x;
    const int tx  = tid % NTX;            // 0..31
    const int ty  = tid / NTX;            // 0..15
    const int m0  = blockIdx.y * BM;
    const int n0  = blockIdx.x * BN;
    const int k0  = blockIdx.z * kspan;

    __shared__ __align__(16) float Xs[2][BM][XSTR];   // 20,480 B
    __shared__ __align__(16) float Ws[2][DK][WSTR];   // 16,896 B

    // Loaders (per k-tile): each operand = 128 rows x 4 quads = 512 float4,
    // exactly one per thread.
    const int lr = tid >> 2, lq = tid & 3;

    const float4* Xg = reinterpret_cast<const float4*>(X + (size_t)(m0 + lr) * D + k0) + lq;
    const float4* Wg = reinterpret_cast<const float4*>(W + (size_t)(n0 + lr) * D + k0) + lq;

    float acc[TM][TN];
#pragma unroll
    for (int i = 0; i < TM; i++)
#pragma unroll
        for (int j = 0; j < TN; j++) acc[i][j] = 0.0f;

    const int ntiles = kspan / DK;

    // Prologue: load + store tile 0, one barrier.
    float4 xv = Xg[0];
    float4 wv = Wg[0];
    *reinterpret_cast<float4*>(&Xs[0][lr][lq * 4]) = xv;
#pragma unroll
    for (int c = 0; c < 4; c++)
        Ws[0][lq * 4 + c][lr] = (&wv.x)[c];
    __syncthreads();

    for (int t = 0; t < ntiles; t++) {
        const int buf = t & 1;
        const bool more = (t + 1 < ntiles);

        // Prefetch next tile into registers (overlaps compute).
        if (more) {
            const int off = (t + 1) * (DK / 4);
            xv = Xg[off];
            wv = Wg[off];
        }

        // Compute on current buffer.
#pragma unroll
        for (int kk = 0; kk < DK; kk += 4) {
            float4 xk[TM];
#pragma unroll
            for (int i = 0; i < TM; i++)
                xk[i] = *reinterpret_cast<const float4*>(&Xs[buf][ty * TM + i][kk]);
            float4 wk[4];
#pragma unroll
            for (int c = 0; c < 4; c++)
                wk[c] = *reinterpret_cast<const float4*>(&Ws[buf][kk + c][tx * TN]);
#pragma unroll
            for (int c = 0; c < 4; c++) {
#pragma unroll
                for (int i = 0; i < TM; i++) {
                    const float xi = (&xk[i].x)[c];
                    acc[i][0] += fminf(xi, wk[c].x);
                    acc[i][1] += fminf(xi, wk[c].y);
                    acc[i][2] += fminf(xi, wk[c].z);
                    acc[i][3] += fminf(xi, wk[c].w);
                }
            }
        }

        // Store prefetched tile into the other buffer, then one barrier.
        if (more) {
            const int nbuf = buf ^ 1;
            *reinterpret_cast<float4*>(&Xs[nbuf][lr][lq * 4]) = xv;
#pragma unroll
            for (int c = 0; c < 4; c++)
                Ws[nbuf][lq * 4 + c][lr] = (&wv.x)[c];
            __syncthreads();
        }
    }

    const size_t zb = (size_t)blockIdx.z * B * O;
#pragma unroll
    for (int i = 0; i < TM; i++) {
        float4 o4;
        o4.x = acc[i][0]; o4.y = acc[i][1]; o4.z = acc[i][2]; o4.w = acc[i][3];
        *reinterpret_cast<float4*>(pC + zb + (size_t)(m0 + ty * TM + i) * O
                                   + (n0 + tx * TN)) = o4;
    }
}

// ---------------------------------------------------------------------------
// Combine NZ=8 partials + epilogue(+relu) + row-sum of result (for next layer).
// One block per output row; 256 threads, 4 cols each (O=1024).
__global__ void combine_epi_rowsum_kernel(const float* __restrict__ pC,
                                          const float* __restrict__ Sx,
                                          const float* __restrict__ Sw,
                                          float* __restrict__ h,
                                          float* __restrict__ Sh,
                                          int B, int O)
{
    const int row = blockIdx.x;
    const int j0  = threadIdx.x * 4;
    const size_t plane = (size_t)B * O;
    const size_t base  = (size_t)row * O + j0;

    float cx = 0.f, cy = 0.f, cz = 0.f, cw = 0.f;
#pragma unroll
    for (int z = 0; z < 8; z++) {
        float4 c = *reinterpret_cast<const float4*>(pC + (size_t)z * plane + base);
        cx += c.x; cy += c.y; cz += c.z; cw += c.w;
    }
    float4 sw = *reinterpret_cast<const float4*>(Sw + j0);
    const float sx = Sx[row];

    float4 o;
    o.x = fmaxf(cx / (0.5f * (sx + sw.x) + EPS), 0.0f);
    o.y = fmaxf(cy / (0.5f * (sx + sw.y) + EPS), 0.0f);
    o.z = fmaxf(cz / (0.5f * (sx + sw.z) + EPS), 0.0f);
    o.w = fmaxf(cw / (0.5f * (sx + sw.w) + EPS), 0.0f);
    *reinterpret_cast<float4*>(h + base) = o;

    // Row-sum of h for the next layer's denominator.
    float s = (o.x + o.y) + (o.z + o.w);
#pragma unroll
    for (int off = 16; off > 0; off >>= 1) s += __shfl_xor_sync(0xFFFFFFFFu, s, off);
    __shared__ float ws[8];
    const int lane = threadIdx.x & 31, w = threadIdx.x >> 5;
    if (lane == 0) ws[w] = s;
    __syncthreads();
    if (w == 0) {
        s = (lane < 8) ? ws[lane] : 0.0f;
#pragma unroll
        for (int off = 4; off > 0; off >>= 1) s += __shfl_xor_sync(0xFFFFFFFFu, s, off);
        if (lane == 0) Sh[row] = s;
    }
}

// Combine nz partials + epilogue (final layer, no relu, no rowsum).
__global__ void combine_final_kernel(const float* __restrict__ pC,
                                     const float* __restrict__ Sx,
                                     const float* __restrict__ Sw,
                                     float* __restrict__ out,
                                     int O, int BO, int nz)
{
    int i = blockIdx.x * blockDim.x + threadIdx.x;
    if (i >= BO) return;
    float c = 0.0f;
    for (int z = 0; z < nz; z++) c += pC[(size_t)z * BO + i];
    const int m = i / O, n = i % O;
    out[i] = c / (0.5f * (Sx[m] + Sw[n]) + EPS);
}

// ---------------------------------------------------------------------------
extern "C" void kernel_launch(void* const* d_in, const int* in_sizes, int n_in,
                              void* d_out, int out_size)
{
    const float* x  = (const float*)d_in[0];   // [256, 1024]
    const float* W1 = (const float*)d_in[1];   // [1024, 1024]
    const float* W2 = (const float*)d_in[2];   // [1024, 1024]
    const float* W3 = (const float*)d_in[3];   // [128, 1024]
    float* out = (float*)d_out;                // [256, 128]

    const int B = 256, H = 1024, C = 128, D = 1024;

    float *h1, *h2, *pC, *Sx, *Sh1, *Sh2, *Sw1, *Sw2, *Sw3;
    cudaGetSymbolAddress((void**)&h1,  g_h1);
    cudaGetSymbolAddress((void**)&h2,  g_h2);
    cudaGetSymbolAddress((void**)&pC,  g_pC);
    cudaGetSymbolAddress((void**)&Sx,  g_Sx);
    cudaGetSymbolAddress((void**)&Sh1, g_Sh1);
    cudaGetSymbolAddress((void**)&Sh2, g_Sh2);
    cudaGetSymbolAddress((void**)&Sw1, g_Sw1);
    cudaGetSymbolAddress((void**)&Sw2, g_Sw2);
    cudaGetSymbolAddress((void**)&Sw3, g_Sw3);

    // Static row sums in one launch.
    rowsum4_kernel<<<256 + 1024 + 1024 + 128, 128>>>(x, Sx, W1, Sw1, W2, Sw2, W3, Sw3, D);

    // Layer 1: x vs W1, split-K=8 (grid 8x2x8 = 128 CTAs), fused combine.
    {
        dim3 grid(H / 128, B / 128, 8);
        tversky_part_kernel<<<grid, 512>>>(x, W1, pC, B, H, D, D / 8);
        combine_epi_rowsum_kernel<<<B, 256>>>(pC, Sx, Sw1, h1, Sh1, B, H);
    }
    // Layer 2: h1 vs W2, split-K=8, fused combine.
    {
        dim3 grid(H / 128, B / 128, 8);
        tversky_part_kernel<<<grid, 512>>>(h1, W2, pC, B, H, H, H / 8);
        combine_epi_rowsum_kernel<<<B, 256>>>(pC, Sh1, Sw2, h2, Sh2, B, H);
    }
    // Layer 3: h2 vs W3, split-K=64 (grid 1x2x64 = 128 CTAs), plain combine.
    {
        const int NZ = 64;
        dim3 grid(C / 128, B / 128, NZ);
        tversky_part_kernel<<<grid, 512>>>(h2, W3, pC, B, C, H, H / NZ);
        combine_final_kernel<<<(B * C + 255) / 256, 256>>>(pC, Sh2, Sw3, out, C, B * C, NZ);
    }
}